// round 2
// baseline (speedup 1.0000x reference)
#include <cuda_runtime.h>
#include <math.h>
#include <stdint.h>

#define W_ 152
#define H_ 100
#define NPIX 15200
#define CIN 512
#define COUT 512
#define KTOT 4608
#define NANCH 136800
#define NSORT 262144
#define PRE_NMS_N 6000
#define POST_NMS_N 300
#define MASK_W 94

__device__ float g_x[COUT * NPIX];
__device__ float g_head[54 * NPIX];
__device__ float4 g_boxes[NANCH];
__device__ unsigned long long g_keys[NSORT];
__device__ float4 g_top_boxes[PRE_NMS_N];
__device__ unsigned long long g_mask[(size_t)PRE_NMS_N * MASK_W];
__device__ int g_sel[POST_NMS_N];

__constant__ float c_anchors[9][4] = {
    {-84.f,  -40.f,  99.f,  55.f},
    {-176.f, -88.f,  191.f, 103.f},
    {-360.f, -184.f, 375.f, 199.f},
    {-56.f,  -56.f,  71.f,  71.f},
    {-120.f, -120.f, 135.f, 135.f},
    {-248.f, -248.f, 263.f, 263.f},
    {-36.f,  -80.f,  51.f,  95.f},
    {-80.f,  -168.f, 95.f,  183.f},
    {-168.f, -344.f, 183.f, 359.f}
};

// ---------- conv3x3 SAME + bias + relu, implicit GEMM: [512][15200] = W[512][4608] x B[4608][15200]
__global__ __launch_bounds__(256) void conv3x3_kernel(
    const float* __restrict__ in, const float* __restrict__ wgt,
    const float* __restrict__ bias)
{
    __shared__ float As[16][132];
    __shared__ float Bs[16][132];
    const int tid = threadIdx.x;
    const int bm = blockIdx.y * 128;
    const int bn = blockIdx.x * 128;
    const int tx = tid & 15, ty = tid >> 4;

    int hr[8], wr[8];
    bool inr[8];
#pragma unroll
    for (int r = 0; r < 8; r++) {
        int e = r * 256 + tid;
        int nn = e & 127;
        int p = bn + nn;
        inr[r] = (p < NPIX);
        int h = (p < NPIX) ? (p / W_) : 0;
        hr[r] = h;
        wr[r] = p - h * W_;
    }

    float acc[8][8];
#pragma unroll
    for (int i = 0; i < 8; i++)
#pragma unroll
        for (int j = 0; j < 8; j++) acc[i][j] = 0.f;

    for (int k0 = 0; k0 < KTOT; k0 += 16) {
#pragma unroll
        for (int r = 0; r < 2; r++) {
            int e = r * 256 + tid;
            int m = e >> 2;
            int kq = (e & 3) << 2;
            float4 v = *reinterpret_cast<const float4*>(
                wgt + (size_t)(bm + m) * KTOT + k0 + kq);
            As[kq + 0][m] = v.x; As[kq + 1][m] = v.y;
            As[kq + 2][m] = v.z; As[kq + 3][m] = v.w;
        }
#pragma unroll
        for (int r = 0; r < 8; r++) {
            int e = r * 256 + tid;
            int kk = e >> 7;
            int nn = e & 127;
            int k = k0 + kk;
            int ic = k / 9;
            int tap = k - ic * 9;
            int ty3 = tap / 3;
            int dy = ty3 - 1;
            int dx = tap - ty3 * 3 - 1;
            float v = 0.f;
            if (inr[r]) {
                int hh = hr[r] + dy, ww = wr[r] + dx;
                if (hh >= 0 && hh < H_ && ww >= 0 && ww < W_)
                    v = __ldg(in + (size_t)ic * NPIX + hh * W_ + ww);
            }
            Bs[kk][nn] = v;
        }
        __syncthreads();
#pragma unroll
        for (int kk = 0; kk < 16; kk++) {
            float a[8], b[8];
            float4 a0 = *reinterpret_cast<float4*>(&As[kk][ty * 8]);
            float4 a1 = *reinterpret_cast<float4*>(&As[kk][ty * 8 + 4]);
            float4 b0 = *reinterpret_cast<float4*>(&Bs[kk][tx * 8]);
            float4 b1 = *reinterpret_cast<float4*>(&Bs[kk][tx * 8 + 4]);
            a[0]=a0.x; a[1]=a0.y; a[2]=a0.z; a[3]=a0.w;
            a[4]=a1.x; a[5]=a1.y; a[6]=a1.z; a[7]=a1.w;
            b[0]=b0.x; b[1]=b0.y; b[2]=b0.z; b[3]=b0.w;
            b[4]=b1.x; b[5]=b1.y; b[6]=b1.z; b[7]=b1.w;
#pragma unroll
            for (int i = 0; i < 8; i++)
#pragma unroll
                for (int j = 0; j < 8; j++)
                    acc[i][j] = __fmaf_rn(a[i], b[j], acc[i][j]);
        }
        __syncthreads();
    }
#pragma unroll
    for (int i = 0; i < 8; i++) {
        int m = bm + ty * 8 + i;
        float bv = bias[m];
#pragma unroll
        for (int j = 0; j < 8; j++) {
            int n = bn + tx * 8 + j;
            if (n < NPIX)
                g_x[(size_t)m * NPIX + n] = fmaxf(__fadd_rn(acc[i][j], bv), 0.f);
        }
    }
}

// ---------- heads: [54][15200] = W2[54][512] x g_x
__global__ __launch_bounds__(256) void head_kernel(
    const float* __restrict__ cls_w, const float* __restrict__ cls_b,
    const float* __restrict__ bbox_w, const float* __restrict__ bbox_b)
{
    __shared__ float As[16][68];
    __shared__ float Bs[16][132];
    const int tid = threadIdx.x;
    const int bn = blockIdx.x * 128;
    const int tx = tid & 15, ty = tid >> 4;

    float acc[4][8];
#pragma unroll
    for (int i = 0; i < 4; i++)
#pragma unroll
        for (int j = 0; j < 8; j++) acc[i][j] = 0.f;

    for (int k0 = 0; k0 < 512; k0 += 16) {
        {
            int m = tid >> 2;
            int kq = (tid & 3) << 2;
            float4 v = make_float4(0.f, 0.f, 0.f, 0.f);
            if (m < 18)
                v = *reinterpret_cast<const float4*>(cls_w + (size_t)m * 512 + k0 + kq);
            else if (m < 54)
                v = *reinterpret_cast<const float4*>(bbox_w + (size_t)(m - 18) * 512 + k0 + kq);
            As[kq + 0][m] = v.x; As[kq + 1][m] = v.y;
            As[kq + 2][m] = v.z; As[kq + 3][m] = v.w;
        }
#pragma unroll
        for (int r = 0; r < 8; r++) {
            int e = r * 256 + tid;
            int kk = e >> 7;
            int nn = e & 127;
            int p = bn + nn;
            Bs[kk][nn] = (p < NPIX) ? g_x[(size_t)(k0 + kk) * NPIX + p] : 0.f;
        }
        __syncthreads();
#pragma unroll
        for (int kk = 0; kk < 16; kk++) {
            float a[4], b[8];
            float4 a0 = *reinterpret_cast<float4*>(&As[kk][ty * 4]);
            float4 b0 = *reinterpret_cast<float4*>(&Bs[kk][tx * 8]);
            float4 b1 = *reinterpret_cast<float4*>(&Bs[kk][tx * 8 + 4]);
            a[0]=a0.x; a[1]=a0.y; a[2]=a0.z; a[3]=a0.w;
            b[0]=b0.x; b[1]=b0.y; b[2]=b0.z; b[3]=b0.w;
            b[4]=b1.x; b[5]=b1.y; b[6]=b1.z; b[7]=b1.w;
#pragma unroll
            for (int i = 0; i < 4; i++)
#pragma unroll
                for (int j = 0; j < 8; j++)
                    acc[i][j] = __fmaf_rn(a[i], b[j], acc[i][j]);
        }
        __syncthreads();
    }
#pragma unroll
    for (int i = 0; i < 4; i++) {
        int m = ty * 4 + i;
        if (m >= 54) continue;
        float bv = (m < 18) ? cls_b[m] : bbox_b[m - 18];
#pragma unroll
        for (int j = 0; j < 8; j++) {
            int n = bn + tx * 8 + j;
            if (n < NPIX)
                g_head[(size_t)m * NPIX + n] = __fadd_rn(acc[i][j], bv);
        }
    }
}

// ---------- decode anchors -> boxes, scores -> sort keys
__global__ void decode_kernel(const float* __restrict__ iminfo)
{
    int idx = blockIdx.x * 256 + threadIdx.x;
    if (idx >= NSORT) return;
    if (idx >= NANCH) { g_keys[idx] = 0ULL; return; }

    int a = idx % 9;
    int p = idx / 9;
    int h = p / W_;
    int w = p - h * W_;

    float s0 = g_head[(size_t)a * NPIX + p];
    float s1 = g_head[(size_t)(9 + a) * NPIX + p];
    float mx = fmaxf(s0, s1);
    float e0 = (float)exp((double)__fsub_rn(s0, mx));
    float e1 = (float)exp((double)__fsub_rn(s1, mx));
    float fg = __fdiv_rn(e1, __fadd_rn(e0, e1));

    float d0 = g_head[(size_t)(18 + a * 4 + 0) * NPIX + p];
    float d1 = g_head[(size_t)(18 + a * 4 + 1) * NPIX + p];
    float d2 = g_head[(size_t)(18 + a * 4 + 2) * NPIX + p];
    float d3 = g_head[(size_t)(18 + a * 4 + 3) * NPIX + p];

    float sx = (float)(w * 16);
    float sy = (float)(h * 16);
    float x1a = c_anchors[a][0] + sx;
    float y1a = c_anchors[a][1] + sy;
    float x2a = c_anchors[a][2] + sx;
    float y2a = c_anchors[a][3] + sy;
    float aw = __fadd_rn(__fsub_rn(x2a, x1a), 1.0f);
    float ah = __fadd_rn(__fsub_rn(y2a, y1a), 1.0f);
    float ax = __fadd_rn(x1a, __fmul_rn(0.5f, aw));
    float ay = __fadd_rn(y1a, __fmul_rn(0.5f, ah));

    float px = __fadd_rn(__fmul_rn(d0, aw), ax);
    float py = __fadd_rn(__fmul_rn(d1, ah), ay);
    float pw = __fmul_rn((float)exp((double)d2), aw);
    float ph = __fmul_rn((float)exp((double)d3), ah);

    float x1 = __fsub_rn(px, __fmul_rn(0.5f, pw));
    float y1 = __fsub_rn(py, __fmul_rn(0.5f, ph));
    float x2 = __fadd_rn(px, __fmul_rn(0.5f, pw));
    float y2 = __fadd_rn(py, __fmul_rn(0.5f, ph));

    float hiX = __fsub_rn(iminfo[1], 1.0f);
    float hiY = __fsub_rn(iminfo[0], 1.0f);
    x1 = fminf(fmaxf(x1, 0.f), hiX);
    y1 = fminf(fmaxf(y1, 0.f), hiY);
    x2 = fminf(fmaxf(x2, 0.f), hiX);
    y2 = fminf(fmaxf(y2, 0.f), hiY);

    float ws = __fadd_rn(__fsub_rn(x2, x1), 1.0f);
    float hs = __fadd_rn(__fsub_rn(y2, y1), 1.0f);
    float msz = __fmul_rn(16.0f, iminfo[2]);
    bool valid = (ws >= msz) && (hs >= msz);
    float score = valid ? fg : -1000000000.0f;

    unsigned u = __float_as_uint(score);
    u = (u & 0x80000000u) ? ~u : (u | 0x80000000u);
    g_keys[idx] = ((unsigned long long)u << 32) | (unsigned)(~(unsigned)idx);
    g_boxes[idx] = make_float4(x1, y1, x2, y2);
}

// ---------- bitonic sort, overall descending
__device__ __forceinline__ bool bt_sw(unsigned long long a, unsigned long long b, bool up)
{
    return up ? (a > b) : (a < b);
}

__global__ __launch_bounds__(1024) void bitonic_local_kernel()
{
    __shared__ unsigned long long s[4096];
    int base = blockIdx.x * 4096;
    for (int e = threadIdx.x; e < 4096; e += 1024) s[e] = g_keys[base + e];
    __syncthreads();
    for (int k = 2; k <= 4096; k <<= 1) {
        for (int j = k >> 1; j > 0; j >>= 1) {
            for (int t = threadIdx.x; t < 2048; t += 1024) {
                int i1 = ((t & ~(j - 1)) << 1) | (t & (j - 1));
                int i2 = i1 + j;
                bool up = (((base + i1) & k) != 0);
                unsigned long long a = s[i1], b = s[i2];
                if (bt_sw(a, b, up)) { s[i1] = b; s[i2] = a; }
            }
            __syncthreads();
        }
    }
    for (int e = threadIdx.x; e < 4096; e += 1024) g_keys[base + e] = s[e];
}

__global__ __launch_bounds__(256) void bitonic_global_kernel(int k, int j)
{
    int t = blockIdx.x * 256 + threadIdx.x;
    int i1 = ((t & ~(j - 1)) << 1) | (t & (j - 1));
    int i2 = i1 + j;
    bool up = ((i1 & k) != 0);
    unsigned long long a = g_keys[i1], b = g_keys[i2];
    if (bt_sw(a, b, up)) { g_keys[i1] = b; g_keys[i2] = a; }
}

__global__ __launch_bounds__(1024) void bitonic_fused_kernel(int k)
{
    __shared__ unsigned long long s[4096];
    int base = blockIdx.x * 4096;
    for (int e = threadIdx.x; e < 4096; e += 1024) s[e] = g_keys[base + e];
    __syncthreads();
    for (int j = 2048; j > 0; j >>= 1) {
        for (int t = threadIdx.x; t < 2048; t += 1024) {
            int i1 = ((t & ~(j - 1)) << 1) | (t & (j - 1));
            int i2 = i1 + j;
            bool up = (((base + i1) & k) != 0);
            unsigned long long a = s[i1], b = s[i2];
            if (bt_sw(a, b, up)) { s[i1] = b; s[i2] = a; }
        }
        __syncthreads();
    }
    for (int e = threadIdx.x; e < 4096; e += 1024) g_keys[base + e] = s[e];
}

__global__ void gather_kernel()
{
    int i = blockIdx.x * 256 + threadIdx.x;
    if (i >= PRE_NMS_N) return;
    unsigned idx = ~((unsigned)(g_keys[i] & 0xFFFFFFFFULL));
    g_top_boxes[i] = g_boxes[idx];
}

// ---------- NMS bitmask
__global__ __launch_bounds__(64) void nms_mask_kernel()
{
    int rb = blockIdx.y, cb = blockIdx.x;
    __shared__ float4 cbox[64];
    int tid = threadIdx.x;
    int col0 = cb * 64;
    int ccount = min(PRE_NMS_N - col0, 64);
    if (tid < ccount) cbox[tid] = g_top_boxes[col0 + tid];
    __syncthreads();
    int i = rb * 64 + tid;
    if (i >= PRE_NMS_N) return;
    float4 bi = g_top_boxes[i];
    float ai = __fmul_rn(__fadd_rn(__fsub_rn(bi.z, bi.x), 1.0f),
                         __fadd_rn(__fsub_rn(bi.w, bi.y), 1.0f));
    unsigned long long bits = 0ULL;
    for (int c = 0; c < ccount; c++) {
        int j = col0 + c;
        if (j <= i) continue;
        float4 bj = cbox[c];
        float xx1 = fmaxf(bi.x, bj.x);
        float yy1 = fmaxf(bi.y, bj.y);
        float xx2 = fminf(bi.z, bj.z);
        float yy2 = fminf(bi.w, bj.w);
        float iw = fmaxf(0.f, __fadd_rn(__fsub_rn(xx2, xx1), 1.0f));
        float ih = fmaxf(0.f, __fadd_rn(__fsub_rn(yy2, yy1), 1.0f));
        float inter = __fmul_rn(iw, ih);
        float aj = __fmul_rn(__fadd_rn(__fsub_rn(bj.z, bj.x), 1.0f),
                             __fadd_rn(__fsub_rn(bj.w, bj.y), 1.0f));
        float iou = __fdiv_rn(inter, __fsub_rn(__fadd_rn(ai, aj), inter));
        if (iou > 0.7f) bits |= (1ULL << c);
    }
    g_mask[(size_t)i * MASK_W + cb] = bits;
}

// ---------- sequential greedy reduce, early exit at 300 kept
__global__ __launch_bounds__(128) void nms_reduce_kernel()
{
    __shared__ unsigned long long remv[MASK_W];
    __shared__ unsigned long long keptbits[MASK_W];
    __shared__ int nkept;
    __shared__ int keptlist[POST_NMS_N];
    __shared__ int cur_keep;
    int tid = threadIdx.x;
    if (tid < MASK_W) { remv[tid] = 0ULL; keptbits[tid] = 0ULL; }
    if (tid == 0) nkept = 0;
    __syncthreads();
    for (int i = 0; i < PRE_NMS_N; i++) {
        if (tid == 0) {
            bool k = !((remv[i >> 6] >> (i & 63)) & 1ULL);
            cur_keep = k ? 1 : 0;
            if (k) {
                keptlist[nkept] = i;
                keptbits[i >> 6] |= (1ULL << (i & 63));
            }
        }
        __syncthreads();
        if (cur_keep) {
            if (tid < MASK_W) remv[tid] |= g_mask[(size_t)i * MASK_W + tid];
            if (tid == 0) nkept++;
            __syncthreads();
            if (nkept >= POST_NMS_N) break;
        }
    }
    __syncthreads();
    if (tid == 0) {
        int n = nkept;
        for (int i = 0; i < PRE_NMS_N && n < POST_NMS_N; i++) {
            if (!((keptbits[i >> 6] >> (i & 63)) & 1ULL)) keptlist[n++] = i;
        }
        nkept = n;
    }
    __syncthreads();
    for (int t = tid; t < POST_NMS_N; t += 128) g_sel[t] = keptlist[t];
}

__global__ void rois_kernel(float* __restrict__ out)
{
    int t = blockIdx.x * 64 + threadIdx.x;
    if (t >= POST_NMS_N) return;
    float4 b = g_top_boxes[g_sel[t]];
    out[t * 5 + 0] = 0.f;
    out[t * 5 + 1] = b.x;
    out[t * 5 + 2] = b.y;
    out[t * 5 + 3] = b.z;
    out[t * 5 + 4] = b.w;
}

extern "C" void kernel_launch(void* const* d_in, const int* in_sizes, int n_in,
                              void* d_out, int out_size)
{
    const float* feature_map = (const float*)d_in[0];
    const float* im_info     = (const float*)d_in[1];
    const float* conv_w      = (const float*)d_in[2];
    const float* conv_b      = (const float*)d_in[3];
    const float* cls_w       = (const float*)d_in[4];
    const float* cls_b       = (const float*)d_in[5];
    const float* bbox_w      = (const float*)d_in[6];
    const float* bbox_b      = (const float*)d_in[7];
    float* out = (float*)d_out;

    dim3 cgrid((NPIX + 127) / 128, 4);
    conv3x3_kernel<<<cgrid, 256>>>(feature_map, conv_w, conv_b);
    head_kernel<<<(NPIX + 127) / 128, 256>>>(cls_w, cls_b, bbox_w, bbox_b);
    decode_kernel<<<NSORT / 256, 256>>>(im_info);

    bitonic_local_kernel<<<NSORT / 4096, 1024>>>();
    for (int k = 8192; k <= NSORT; k <<= 1) {
        for (int j = k >> 1; j >= 4096; j >>= 1)
            bitonic_global_kernel<<<NSORT / 512, 256>>>(k, j);
        bitonic_fused_kernel<<<NSORT / 4096, 1024>>>(k);
    }

    gather_kernel<<<(PRE_NMS_N + 255) / 256, 256>>>();
    dim3 mgrid(MASK_W, MASK_W);
    nms_mask_kernel<<<mgrid, 64>>>();
    nms_reduce_kernel<<<1, 128>>>();
    rois_kernel<<<(POST_NMS_N + 63) / 64, 64>>>(out);
}

// round 3
// speedup vs baseline: 1.3333x; 1.3333x over previous
#include <cuda_runtime.h>
#include <math.h>
#include <stdint.h>

#define W_ 152
#define H_ 100
#define NPIX 15200
#define CIN 512
#define COUT 512
#define KTOT 4608
#define NANCH 136800
#define NSORT 262144
#define PRE_NMS_N 6000
#define POST_NMS_N 300
#define MASK_W 94

__device__ float g_wT[COUT * KTOT];          // weights reordered: [oc][tap*512+ic]
__device__ float g_x[COUT * NPIX];
__device__ float g_head[54 * NPIX];
__device__ float4 g_boxes[NANCH];
__device__ unsigned long long g_keys[NSORT];
__device__ float4 g_top_boxes[PRE_NMS_N];
__device__ unsigned long long g_mask[(size_t)PRE_NMS_N * MASK_W];
__device__ int g_sel[POST_NMS_N];

__constant__ float c_anchors[9][4] = {
    {-84.f,  -40.f,  99.f,  55.f},
    {-176.f, -88.f,  191.f, 103.f},
    {-360.f, -184.f, 375.f, 199.f},
    {-56.f,  -56.f,  71.f,  71.f},
    {-120.f, -120.f, 135.f, 135.f},
    {-248.f, -248.f, 263.f, 263.f},
    {-36.f,  -80.f,  51.f,  95.f},
    {-80.f,  -168.f, 95.f,  183.f},
    {-168.f, -344.f, 183.f, 359.f}
};

// ---------------- weight reorder: g_wT[oc][tap*512+ic] = conv_w[oc][ic*9+tap]
__global__ __launch_bounds__(256) void wtrans_kernel(const float* __restrict__ wgt)
{
    int idx = blockIdx.x * 256 + threadIdx.x;
    if (idx >= COUT * KTOT) return;
    int oc = idx / KTOT;
    int r = idx - oc * KTOT;
    int tap = r >> 9;
    int ic = r & 511;
    g_wT[idx] = wgt[(size_t)oc * KTOT + ic * 9 + tap];
}

// ---------------- conv3x3 SAME + bias + relu, implicit GEMM with packed f32x2 FMA
// C[512][15200] = A[512][4608] x B[4608][15200], k = tap*512 + ic
// BM=128, BN=128, BK=8, 128 threads, per-thread 8(m) x 16(n)
__global__ __launch_bounds__(128) void conv3x3_kernel(
    const float* __restrict__ in, const float* __restrict__ bias)
{
    __shared__ float As[2][8][128];
    __shared__ float Bs[2][8][128];

    const int tid = threadIdx.x;
    const int tx = tid & 7;        // n-group selector
    const int ty = tid >> 3;       // m selector (0..15)
    const int bm = blockIdx.y * 128;
    const int bn = blockIdx.x * 128;

    // pixel for this thread's B loads
    const int p = bn + tid;
    const bool pv = (p < NPIX);
    const int ph = pv ? (p / W_) : 0;
    const int pw = p - ph * W_;

    const float4* wrow = reinterpret_cast<const float4*>(g_wT + (size_t)(bm + tid) * KTOT);

    unsigned long long acc[8][8];
#pragma unroll
    for (int i = 0; i < 8; i++)
#pragma unroll
        for (int j = 0; j < 8; j++) acc[i][j] = 0ULL;

    float Areg[8], Breg[8];

    // ---- load tile for iteration 'it' into registers
    auto loadTile = [&](int it, float* ar, float* br) {
        int k0 = it * 8;
        float4 a0 = wrow[k0 >> 2];
        float4 a1 = wrow[(k0 >> 2) + 1];
        ar[0]=a0.x; ar[1]=a0.y; ar[2]=a0.z; ar[3]=a0.w;
        ar[4]=a1.x; ar[5]=a1.y; ar[6]=a1.z; ar[7]=a1.w;
        int tap = k0 >> 9;
        int ty3 = tap / 3;
        int dy = ty3 - 1;
        int dx = tap - ty3 * 3 - 1;
        int hh = ph + dy, ww = pw + dx;
        bool valid = pv && (hh >= 0) && (hh < H_) && (ww >= 0) && (ww < W_);
        int ic0 = k0 & 511;
        const float* src = in + (size_t)ic0 * NPIX + p + dy * W_ + dx;
#pragma unroll
        for (int r = 0; r < 8; r++)
            br[r] = valid ? __ldg(src + (size_t)r * NPIX) : 0.f;
    };
    auto storeTile = [&](int buf, const float* ar, const float* br) {
#pragma unroll
        for (int kk = 0; kk < 8; kk++) As[buf][kk][tid] = ar[kk];
#pragma unroll
        for (int kk = 0; kk < 8; kk++) Bs[buf][kk][tid] = br[kk];
    };

    loadTile(0, Areg, Breg);
    storeTile(0, Areg, Breg);
    __syncthreads();

    int cur = 0;
    const int NIT = KTOT / 8;   // 576
    for (int it = 0; it < NIT; it++) {
        bool more = (it + 1 < NIT);
        if (more) loadTile(it + 1, Areg, Breg);

#pragma unroll
        for (int kk = 0; kk < 8; kk++) {
            const float4* arow = reinterpret_cast<const float4*>(&As[cur][kk][0]);
            const ulonglong2* brow = reinterpret_cast<const ulonglong2*>(&Bs[cur][kk][0]);
            unsigned long long b2[8];
#pragma unroll
            for (int q = 0; q < 4; q++) {
                ulonglong2 t = brow[tx + q * 8];
                b2[2 * q] = t.x;
                b2[2 * q + 1] = t.y;
            }
            float4 a0 = arow[ty];
            float4 a1 = arow[ty + 16];
            float av[8];
            av[0]=a0.x; av[1]=a0.y; av[2]=a0.z; av[3]=a0.w;
            av[4]=a1.x; av[5]=a1.y; av[6]=a1.z; av[7]=a1.w;
            unsigned long long a2[8];
#pragma unroll
            for (int s = 0; s < 8; s++)
                asm("mov.b64 %0, {%1, %1};" : "=l"(a2[s]) : "f"(av[s]));
#pragma unroll
            for (int s = 0; s < 8; s++)
#pragma unroll
                for (int j = 0; j < 8; j++)
                    asm("fma.rn.f32x2 %0, %1, %2, %0;"
                        : "+l"(acc[s][j]) : "l"(a2[s]), "l"(b2[j]));
        }

        if (more) {
            storeTile(cur ^ 1, Areg, Breg);
            __syncthreads();
            cur ^= 1;
        }
    }

    // epilogue: bias + relu, store float2 pairs
#pragma unroll
    for (int r = 0; r < 2; r++)
#pragma unroll
        for (int s = 0; s < 4; s++) {
            int m = bm + r * 64 + ty * 4 + s;
            float bv = bias[m];
#pragma unroll
            for (int q = 0; q < 4; q++)
#pragma unroll
                for (int t = 0; t < 2; t++) {
                    int n = bn + q * 32 + tx * 4 + t * 2;
                    if (n < NPIX) {
                        unsigned long long v = acc[r * 4 + s][q * 2 + t];
                        float lo, hi;
                        asm("mov.b64 {%0, %1}, %2;" : "=f"(lo), "=f"(hi) : "l"(v));
                        lo = fmaxf(__fadd_rn(lo, bv), 0.f);
                        hi = fmaxf(__fadd_rn(hi, bv), 0.f);
                        *reinterpret_cast<float2*>(&g_x[(size_t)m * NPIX + n]) =
                            make_float2(lo, hi);
                    }
                }
        }
}

// ---------- heads: [54][15200] = W2[54][512] x g_x
__global__ __launch_bounds__(256) void head_kernel(
    const float* __restrict__ cls_w, const float* __restrict__ cls_b,
    const float* __restrict__ bbox_w, const float* __restrict__ bbox_b)
{
    __shared__ float As[16][68];
    __shared__ float Bs[16][132];
    const int tid = threadIdx.x;
    const int bn = blockIdx.x * 128;
    const int tx = tid & 15, ty = tid >> 4;

    float acc[4][8];
#pragma unroll
    for (int i = 0; i < 4; i++)
#pragma unroll
        for (int j = 0; j < 8; j++) acc[i][j] = 0.f;

    for (int k0 = 0; k0 < 512; k0 += 16) {
        {
            int m = tid >> 2;
            int kq = (tid & 3) << 2;
            float4 v = make_float4(0.f, 0.f, 0.f, 0.f);
            if (m < 18)
                v = *reinterpret_cast<const float4*>(cls_w + (size_t)m * 512 + k0 + kq);
            else if (m < 54)
                v = *reinterpret_cast<const float4*>(bbox_w + (size_t)(m - 18) * 512 + k0 + kq);
            As[kq + 0][m] = v.x; As[kq + 1][m] = v.y;
            As[kq + 2][m] = v.z; As[kq + 3][m] = v.w;
        }
#pragma unroll
        for (int r = 0; r < 8; r++) {
            int e = r * 256 + tid;
            int kk = e >> 7;
            int nn = e & 127;
            int p = bn + nn;
            Bs[kk][nn] = (p < NPIX) ? g_x[(size_t)(k0 + kk) * NPIX + p] : 0.f;
        }
        __syncthreads();
#pragma unroll
        for (int kk = 0; kk < 16; kk++) {
            float a[4], b[8];
            float4 a0 = *reinterpret_cast<float4*>(&As[kk][ty * 4]);
            float4 b0 = *reinterpret_cast<float4*>(&Bs[kk][tx * 8]);
            float4 b1 = *reinterpret_cast<float4*>(&Bs[kk][tx * 8 + 4]);
            a[0]=a0.x; a[1]=a0.y; a[2]=a0.z; a[3]=a0.w;
            b[0]=b0.x; b[1]=b0.y; b[2]=b0.z; b[3]=b0.w;
            b[4]=b1.x; b[5]=b1.y; b[6]=b1.z; b[7]=b1.w;
#pragma unroll
            for (int i = 0; i < 4; i++)
#pragma unroll
                for (int j = 0; j < 8; j++)
                    acc[i][j] = __fmaf_rn(a[i], b[j], acc[i][j]);
        }
        __syncthreads();
    }
#pragma unroll
    for (int i = 0; i < 4; i++) {
        int m = ty * 4 + i;
        if (m >= 54) continue;
        float bv = (m < 18) ? cls_b[m] : bbox_b[m - 18];
#pragma unroll
        for (int j = 0; j < 8; j++) {
            int n = bn + tx * 8 + j;
            if (n < NPIX)
                g_head[(size_t)m * NPIX + n] = __fadd_rn(acc[i][j], bv);
        }
    }
}

// ---------- decode anchors -> boxes, scores -> sort keys
__global__ void decode_kernel(const float* __restrict__ iminfo)
{
    int idx = blockIdx.x * 256 + threadIdx.x;
    if (idx >= NSORT) return;
    if (idx >= NANCH) { g_keys[idx] = 0ULL; return; }

    int a = idx % 9;
    int p = idx / 9;
    int h = p / W_;
    int w = p - h * W_;

    float s0 = g_head[(size_t)a * NPIX + p];
    float s1 = g_head[(size_t)(9 + a) * NPIX + p];
    float mx = fmaxf(s0, s1);
    float e0 = (float)exp((double)__fsub_rn(s0, mx));
    float e1 = (float)exp((double)__fsub_rn(s1, mx));
    float fg = __fdiv_rn(e1, __fadd_rn(e0, e1));

    float d0 = g_head[(size_t)(18 + a * 4 + 0) * NPIX + p];
    float d1 = g_head[(size_t)(18 + a * 4 + 1) * NPIX + p];
    float d2 = g_head[(size_t)(18 + a * 4 + 2) * NPIX + p];
    float d3 = g_head[(size_t)(18 + a * 4 + 3) * NPIX + p];

    float sx = (float)(w * 16);
    float sy = (float)(h * 16);
    float x1a = c_anchors[a][0] + sx;
    float y1a = c_anchors[a][1] + sy;
    float x2a = c_anchors[a][2] + sx;
    float y2a = c_anchors[a][3] + sy;
    float aw = __fadd_rn(__fsub_rn(x2a, x1a), 1.0f);
    float ah = __fadd_rn(__fsub_rn(y2a, y1a), 1.0f);
    float ax = __fadd_rn(x1a, __fmul_rn(0.5f, aw));
    float ay = __fadd_rn(y1a, __fmul_rn(0.5f, ah));

    float px = __fadd_rn(__fmul_rn(d0, aw), ax);
    float py = __fadd_rn(__fmul_rn(d1, ah), ay);
    float pwv = __fmul_rn((float)exp((double)d2), aw);
    float phv = __fmul_rn((float)exp((double)d3), ah);

    float x1 = __fsub_rn(px, __fmul_rn(0.5f, pwv));
    float y1 = __fsub_rn(py, __fmul_rn(0.5f, phv));
    float x2 = __fadd_rn(px, __fmul_rn(0.5f, pwv));
    float y2 = __fadd_rn(py, __fmul_rn(0.5f, phv));

    float hiX = __fsub_rn(iminfo[1], 1.0f);
    float hiY = __fsub_rn(iminfo[0], 1.0f);
    x1 = fminf(fmaxf(x1, 0.f), hiX);
    y1 = fminf(fmaxf(y1, 0.f), hiY);
    x2 = fminf(fmaxf(x2, 0.f), hiX);
    y2 = fminf(fmaxf(y2, 0.f), hiY);

    float ws = __fadd_rn(__fsub_rn(x2, x1), 1.0f);
    float hs = __fadd_rn(__fsub_rn(y2, y1), 1.0f);
    float msz = __fmul_rn(16.0f, iminfo[2]);
    bool valid = (ws >= msz) && (hs >= msz);
    float score = valid ? fg : -1000000000.0f;

    unsigned u = __float_as_uint(score);
    u = (u & 0x80000000u) ? ~u : (u | 0x80000000u);
    g_keys[idx] = ((unsigned long long)u << 32) | (unsigned)(~(unsigned)idx);
    g_boxes[idx] = make_float4(x1, y1, x2, y2);
}

// ---------- bitonic sort, overall descending
__device__ __forceinline__ bool bt_sw(unsigned long long a, unsigned long long b, bool up)
{
    return up ? (a > b) : (a < b);
}

__global__ __launch_bounds__(1024) void bitonic_local_kernel()
{
    __shared__ unsigned long long s[4096];
    int base = blockIdx.x * 4096;
    for (int e = threadIdx.x; e < 4096; e += 1024) s[e] = g_keys[base + e];
    __syncthreads();
    for (int k = 2; k <= 4096; k <<= 1) {
        for (int j = k >> 1; j > 0; j >>= 1) {
            for (int t = threadIdx.x; t < 2048; t += 1024) {
                int i1 = ((t & ~(j - 1)) << 1) | (t & (j - 1));
                int i2 = i1 + j;
                bool up = (((base + i1) & k) != 0);
                unsigned long long a = s[i1], b = s[i2];
                if (bt_sw(a, b, up)) { s[i1] = b; s[i2] = a; }
            }
            __syncthreads();
        }
    }
    for (int e = threadIdx.x; e < 4096; e += 1024) g_keys[base + e] = s[e];
}

__global__ __launch_bounds__(256) void bitonic_global_kernel(int k, int j)
{
    int t = blockIdx.x * 256 + threadIdx.x;
    int i1 = ((t & ~(j - 1)) << 1) | (t & (j - 1));
    int i2 = i1 + j;
    bool up = ((i1 & k) != 0);
    unsigned long long a = g_keys[i1], b = g_keys[i2];
    if (bt_sw(a, b, up)) { g_keys[i1] = b; g_keys[i2] = a; }
}

__global__ __launch_bounds__(1024) void bitonic_fused_kernel(int k)
{
    __shared__ unsigned long long s[4096];
    int base = blockIdx.x * 4096;
    for (int e = threadIdx.x; e < 4096; e += 1024) s[e] = g_keys[base + e];
    __syncthreads();
    for (int j = 2048; j > 0; j >>= 1) {
        for (int t = threadIdx.x; t < 2048; t += 1024) {
            int i1 = ((t & ~(j - 1)) << 1) | (t & (j - 1));
            int i2 = i1 + j;
            bool up = (((base + i1) & k) != 0);
            unsigned long long a = s[i1], b = s[i2];
            if (bt_sw(a, b, up)) { s[i1] = b; s[i2] = a; }
        }
        __syncthreads();
    }
    for (int e = threadIdx.x; e < 4096; e += 1024) g_keys[base + e] = s[e];
}

__global__ void gather_kernel()
{
    int i = blockIdx.x * 256 + threadIdx.x;
    if (i >= PRE_NMS_N) return;
    unsigned idx = ~((unsigned)(g_keys[i] & 0xFFFFFFFFULL));
    g_top_boxes[i] = g_boxes[idx];
}

// ---------- NMS bitmask (upper triangle only; lower stays BSS zero)
__global__ __launch_bounds__(64) void nms_mask_kernel()
{
    int rb = blockIdx.y, cb = blockIdx.x;
    if (cb < rb) return;
    __shared__ float4 cbox[64];
    int tid = threadIdx.x;
    int col0 = cb * 64;
    int ccount = min(PRE_NMS_N - col0, 64);
    if (tid < ccount) cbox[tid] = g_top_boxes[col0 + tid];
    __syncthreads();
    int i = rb * 64 + tid;
    if (i >= PRE_NMS_N) return;
    float4 bi = g_top_boxes[i];
    float ai = __fmul_rn(__fadd_rn(__fsub_rn(bi.z, bi.x), 1.0f),
                         __fadd_rn(__fsub_rn(bi.w, bi.y), 1.0f));
    unsigned long long bits = 0ULL;
    for (int c = 0; c < ccount; c++) {
        int j = col0 + c;
        if (j <= i) continue;
        float4 bj = cbox[c];
        float xx1 = fmaxf(bi.x, bj.x);
        float yy1 = fmaxf(bi.y, bj.y);
        float xx2 = fminf(bi.z, bj.z);
        float yy2 = fminf(bi.w, bj.w);
        float iw = fmaxf(0.f, __fadd_rn(__fsub_rn(xx2, xx1), 1.0f));
        float ih = fmaxf(0.f, __fadd_rn(__fsub_rn(yy2, yy1), 1.0f));
        float inter = __fmul_rn(iw, ih);
        float aj = __fmul_rn(__fadd_rn(__fsub_rn(bj.z, bj.x), 1.0f),
                             __fadd_rn(__fsub_rn(bj.w, bj.y), 1.0f));
        float iou = __fdiv_rn(inter, __fsub_rn(__fadd_rn(ai, aj), inter));
        if (iou > 0.7f) bits |= (1ULL << c);
    }
    g_mask[(size_t)i * MASK_W + cb] = bits;
}

// ---------- warp-synchronous greedy reduce (no block barriers in loop)
__global__ __launch_bounds__(32) void nms_reduce_kernel()
{
    __shared__ int keptlist[POST_NMS_N];
    int lane = threadIdx.x;
    unsigned long long remv0 = 0, remv1 = 0, remv2 = 0;
    unsigned long long kb0 = 0, kb1 = 0, kb2 = 0;
    int nkept = 0;
    for (int i = 0; i < PRE_NMS_N && nkept < POST_NMS_N; i++) {
        int w = i >> 6, b = i & 63;
        unsigned long long cand = (w < 32) ? remv0 : ((w < 64) ? remv1 : remv2);
        int owner = (w < 32) ? w : ((w < 64) ? w - 32 : w - 64);
        unsigned long long word = __shfl_sync(0xffffffffu, cand, owner);
        if (!((word >> b) & 1ULL)) {
            if (lane == 0) keptlist[nkept] = i;
            if (w < 32) { if (lane == w) kb0 |= 1ULL << b; }
            else if (w < 64) { if (lane == w - 32) kb1 |= 1ULL << b; }
            else { if (lane == w - 64) kb2 |= 1ULL << b; }
            const unsigned long long* row = g_mask + (size_t)i * MASK_W;
            remv0 |= row[lane];
            remv1 |= row[lane + 32];
            if (lane + 64 < MASK_W) remv2 |= row[lane + 64];
            nkept++;
        }
    }
    __syncwarp();
    for (int i = 0; i < PRE_NMS_N && nkept < POST_NMS_N; i++) {
        int w = i >> 6, b = i & 63;
        unsigned long long cand = (w < 32) ? kb0 : ((w < 64) ? kb1 : kb2);
        int owner = (w < 32) ? w : ((w < 64) ? w - 32 : w - 64);
        unsigned long long word = __shfl_sync(0xffffffffu, cand, owner);
        if (!((word >> b) & 1ULL)) {
            if (lane == 0) keptlist[nkept] = i;
            nkept++;
        }
    }
    __syncwarp();
    for (int t = lane; t < POST_NMS_N; t += 32) g_sel[t] = keptlist[t];
}

__global__ void rois_kernel(float* __restrict__ out)
{
    int t = blockIdx.x * 64 + threadIdx.x;
    if (t >= POST_NMS_N) return;
    float4 b = g_top_boxes[g_sel[t]];
    out[t * 5 + 0] = 0.f;
    out[t * 5 + 1] = b.x;
    out[t * 5 + 2] = b.y;
    out[t * 5 + 3] = b.z;
    out[t * 5 + 4] = b.w;
}

extern "C" void kernel_launch(void* const* d_in, const int* in_sizes, int n_in,
                              void* d_out, int out_size)
{
    const float* feature_map = (const float*)d_in[0];
    const float* im_info     = (const float*)d_in[1];
    const float* conv_w      = (const float*)d_in[2];
    const float* conv_b      = (const float*)d_in[3];
    const float* cls_w       = (const float*)d_in[4];
    const float* cls_b       = (const float*)d_in[5];
    const float* bbox_w      = (const float*)d_in[6];
    const float* bbox_b      = (const float*)d_in[7];
    float* out = (float*)d_out;

    wtrans_kernel<<<(COUT * KTOT + 255) / 256, 256>>>(conv_w);

    dim3 cgrid((NPIX + 127) / 128, 4);
    conv3x3_kernel<<<cgrid, 128>>>(feature_map, conv_b);

    head_kernel<<<(NPIX + 127) / 128, 256>>>(cls_w, cls_b, bbox_w, bbox_b);
    decode_kernel<<<NSORT / 256, 256>>>(im_info);

    bitonic_local_kernel<<<NSORT / 4096, 1024>>>();
    for (int k = 8192; k <= NSORT; k <<= 1) {
        for (int j = k >> 1; j >= 4096; j >>= 1)
            bitonic_global_kernel<<<NSORT / 512, 256>>>(k, j);
        bitonic_fused_kernel<<<NSORT / 4096, 1024>>>(k);
    }

    gather_kernel<<<(PRE_NMS_N + 255) / 256, 256>>>();
    dim3 mgrid(MASK_W, MASK_W);
    nms_mask_kernel<<<mgrid, 64>>>();
    nms_reduce_kernel<<<1, 32>>>();
    rois_kernel<<<(POST_NMS_N + 63) / 64, 64>>>(out);
}

// round 4
// speedup vs baseline: 1.3399x; 1.0050x over previous
#include <cuda_runtime.h>
#include <math.h>
#include <stdint.h>

#define W_ 152
#define H_ 100
#define NPIX 15200
#define CIN 512
#define COUT 512
#define KTOT 4608
#define NANCH 136800
#define NCAND 8192
#define NHIST 4096
#define PRE_NMS_N 6000
#define POST_NMS_N 300
#define MASK_W 94

__device__ float g_wT[COUT * KTOT];
__device__ float g_x[COUT * NPIX];
__device__ float g_head[54 * NPIX];
__device__ float4 g_boxes[NANCH];
__device__ unsigned long long g_keys[NANCH];
__device__ unsigned long long g_cand[NCAND];
__device__ int g_hist1[NHIST];
__device__ int g_hist2[NHIST];
__device__ int g_b1;
__device__ int g_above1;
__device__ unsigned g_T24;
__device__ int g_count;
__device__ float4 g_top_boxes[PRE_NMS_N];
__device__ unsigned long long g_mask[(size_t)PRE_NMS_N * MASK_W];
__device__ int g_sel[POST_NMS_N];

__constant__ float c_anchors[9][4] = {
    {-84.f,  -40.f,  99.f,  55.f},
    {-176.f, -88.f,  191.f, 103.f},
    {-360.f, -184.f, 375.f, 199.f},
    {-56.f,  -56.f,  71.f,  71.f},
    {-120.f, -120.f, 135.f, 135.f},
    {-248.f, -248.f, 263.f, 263.f},
    {-36.f,  -80.f,  51.f,  95.f},
    {-80.f,  -168.f, 95.f,  183.f},
    {-168.f, -344.f, 183.f, 359.f}
};

// ---------------- weight reorder: g_wT[oc][tap*512+ic] = conv_w[oc][ic*9+tap]
__global__ __launch_bounds__(256) void wtrans_kernel(const float* __restrict__ wgt)
{
    int idx = blockIdx.x * 256 + threadIdx.x;
    if (idx >= COUT * KTOT) return;
    int oc = idx / KTOT;
    int r = idx - oc * KTOT;
    int tap = r >> 9;
    int ic = r & 511;
    g_wT[idx] = wgt[(size_t)oc * KTOT + ic * 9 + tap];
}

// ---------------- conv3x3 SAME + bias + relu, implicit GEMM with packed f32x2 FMA
__global__ __launch_bounds__(128) void conv3x3_kernel(
    const float* __restrict__ in, const float* __restrict__ bias)
{
    __shared__ float As[2][8][128];
    __shared__ float Bs[2][8][128];

    const int tid = threadIdx.x;
    const int tx = tid & 7;
    const int ty = tid >> 3;
    const int bm = blockIdx.y * 128;
    const int bn = blockIdx.x * 128;

    const int p = bn + tid;
    const bool pv = (p < NPIX);
    const int ph = pv ? (p / W_) : 0;
    const int pw = p - ph * W_;

    const float4* wrow = reinterpret_cast<const float4*>(g_wT + (size_t)(bm + tid) * KTOT);

    unsigned long long acc[8][8];
#pragma unroll
    for (int i = 0; i < 8; i++)
#pragma unroll
        for (int j = 0; j < 8; j++) acc[i][j] = 0ULL;

    float Areg[8], Breg[8];

    auto loadTile = [&](int it, float* ar, float* br) {
        int k0 = it * 8;
        float4 a0 = wrow[k0 >> 2];
        float4 a1 = wrow[(k0 >> 2) + 1];
        ar[0]=a0.x; ar[1]=a0.y; ar[2]=a0.z; ar[3]=a0.w;
        ar[4]=a1.x; ar[5]=a1.y; ar[6]=a1.z; ar[7]=a1.w;
        int tap = k0 >> 9;
        int ty3 = tap / 3;
        int dy = ty3 - 1;
        int dx = tap - ty3 * 3 - 1;
        int hh = ph + dy, ww = pw + dx;
        bool valid = pv && (hh >= 0) && (hh < H_) && (ww >= 0) && (ww < W_);
        int ic0 = k0 & 511;
        const float* src = in + (size_t)ic0 * NPIX + p + dy * W_ + dx;
#pragma unroll
        for (int r = 0; r < 8; r++)
            br[r] = valid ? __ldg(src + (size_t)r * NPIX) : 0.f;
    };
    auto storeTile = [&](int buf, const float* ar, const float* br) {
#pragma unroll
        for (int kk = 0; kk < 8; kk++) As[buf][kk][tid] = ar[kk];
#pragma unroll
        for (int kk = 0; kk < 8; kk++) Bs[buf][kk][tid] = br[kk];
    };

    loadTile(0, Areg, Breg);
    storeTile(0, Areg, Breg);
    __syncthreads();

    int cur = 0;
    const int NIT = KTOT / 8;
    for (int it = 0; it < NIT; it++) {
        bool more = (it + 1 < NIT);
        if (more) loadTile(it + 1, Areg, Breg);

#pragma unroll
        for (int kk = 0; kk < 8; kk++) {
            const float4* arow = reinterpret_cast<const float4*>(&As[cur][kk][0]);
            const ulonglong2* brow = reinterpret_cast<const ulonglong2*>(&Bs[cur][kk][0]);
            unsigned long long b2[8];
#pragma unroll
            for (int q = 0; q < 4; q++) {
                ulonglong2 t = brow[tx + q * 8];
                b2[2 * q] = t.x;
                b2[2 * q + 1] = t.y;
            }
            float4 a0 = arow[ty];
            float4 a1 = arow[ty + 16];
            float av[8];
            av[0]=a0.x; av[1]=a0.y; av[2]=a0.z; av[3]=a0.w;
            av[4]=a1.x; av[5]=a1.y; av[6]=a1.z; av[7]=a1.w;
            unsigned long long a2[8];
#pragma unroll
            for (int s = 0; s < 8; s++)
                asm("mov.b64 %0, {%1, %1};" : "=l"(a2[s]) : "f"(av[s]));
#pragma unroll
            for (int s = 0; s < 8; s++)
#pragma unroll
                for (int j = 0; j < 8; j++)
                    asm("fma.rn.f32x2 %0, %1, %2, %0;"
                        : "+l"(acc[s][j]) : "l"(a2[s]), "l"(b2[j]));
        }

        if (more) {
            storeTile(cur ^ 1, Areg, Breg);
            __syncthreads();
            cur ^= 1;
        }
    }

#pragma unroll
    for (int r = 0; r < 2; r++)
#pragma unroll
        for (int s = 0; s < 4; s++) {
            int m = bm + r * 64 + ty * 4 + s;
            float bv = bias[m];
#pragma unroll
            for (int q = 0; q < 4; q++)
#pragma unroll
                for (int t = 0; t < 2; t++) {
                    int n = bn + q * 32 + tx * 4 + t * 2;
                    if (n < NPIX) {
                        unsigned long long v = acc[r * 4 + s][q * 2 + t];
                        float lo, hi;
                        asm("mov.b64 {%0, %1}, %2;" : "=f"(lo), "=f"(hi) : "l"(v));
                        lo = fmaxf(__fadd_rn(lo, bv), 0.f);
                        hi = fmaxf(__fadd_rn(hi, bv), 0.f);
                        *reinterpret_cast<float2*>(&g_x[(size_t)m * NPIX + n]) =
                            make_float2(lo, hi);
                    }
                }
        }
}

// ---------- heads: [54][15200] = W2[54][512] x g_x
__global__ __launch_bounds__(256) void head_kernel(
    const float* __restrict__ cls_w, const float* __restrict__ cls_b,
    const float* __restrict__ bbox_w, const float* __restrict__ bbox_b)
{
    __shared__ float As[16][68];
    __shared__ float Bs[16][132];
    const int tid = threadIdx.x;
    const int bn = blockIdx.x * 128;
    const int tx = tid & 15, ty = tid >> 4;

    float acc[4][8];
#pragma unroll
    for (int i = 0; i < 4; i++)
#pragma unroll
        for (int j = 0; j < 8; j++) acc[i][j] = 0.f;

    for (int k0 = 0; k0 < 512; k0 += 16) {
        {
            int m = tid >> 2;
            int kq = (tid & 3) << 2;
            float4 v = make_float4(0.f, 0.f, 0.f, 0.f);
            if (m < 18)
                v = *reinterpret_cast<const float4*>(cls_w + (size_t)m * 512 + k0 + kq);
            else if (m < 54)
                v = *reinterpret_cast<const float4*>(bbox_w + (size_t)(m - 18) * 512 + k0 + kq);
            As[kq + 0][m] = v.x; As[kq + 1][m] = v.y;
            As[kq + 2][m] = v.z; As[kq + 3][m] = v.w;
        }
#pragma unroll
        for (int r = 0; r < 8; r++) {
            int e = r * 256 + tid;
            int kk = e >> 7;
            int nn = e & 127;
            int p = bn + nn;
            Bs[kk][nn] = (p < NPIX) ? g_x[(size_t)(k0 + kk) * NPIX + p] : 0.f;
        }
        __syncthreads();
#pragma unroll
        for (int kk = 0; kk < 16; kk++) {
            float a[4], b[8];
            float4 a0 = *reinterpret_cast<float4*>(&As[kk][ty * 4]);
            float4 b0 = *reinterpret_cast<float4*>(&Bs[kk][tx * 8]);
            float4 b1 = *reinterpret_cast<float4*>(&Bs[kk][tx * 8 + 4]);
            a[0]=a0.x; a[1]=a0.y; a[2]=a0.z; a[3]=a0.w;
            b[0]=b0.x; b[1]=b0.y; b[2]=b0.z; b[3]=b0.w;
            b[4]=b1.x; b[5]=b1.y; b[6]=b1.z; b[7]=b1.w;
#pragma unroll
            for (int i = 0; i < 4; i++)
#pragma unroll
                for (int j = 0; j < 8; j++)
                    acc[i][j] = __fmaf_rn(a[i], b[j], acc[i][j]);
        }
        __syncthreads();
    }
#pragma unroll
    for (int i = 0; i < 4; i++) {
        int m = ty * 4 + i;
        if (m >= 54) continue;
        float bv = (m < 18) ? cls_b[m] : bbox_b[m - 18];
#pragma unroll
        for (int j = 0; j < 8; j++) {
            int n = bn + tx * 8 + j;
            if (n < NPIX)
                g_head[(size_t)m * NPIX + n] = __fadd_rn(acc[i][j], bv);
        }
    }
}

// ---------- zero selection scratch (runs every launch, before decode)
__global__ void zero_sel_kernel()
{
    int idx = blockIdx.x * 256 + threadIdx.x;
    if (idx < NCAND) g_cand[idx] = 0ULL;
    if (idx < NHIST) { g_hist1[idx] = 0; g_hist2[idx] = 0; }
    if (idx == 0) g_count = 0;
}

// ---------- decode anchors -> boxes, scores -> keys + level-1 histogram
__global__ void decode_kernel(const float* __restrict__ iminfo)
{
    int idx = blockIdx.x * 256 + threadIdx.x;
    if (idx >= NANCH) return;

    int a = idx % 9;
    int p = idx / 9;
    int h = p / W_;
    int w = p - h * W_;

    float s0 = g_head[(size_t)a * NPIX + p];
    float s1 = g_head[(size_t)(9 + a) * NPIX + p];
    float mx = fmaxf(s0, s1);
    float e0 = (float)exp((double)__fsub_rn(s0, mx));
    float e1 = (float)exp((double)__fsub_rn(s1, mx));
    float fg = __fdiv_rn(e1, __fadd_rn(e0, e1));

    float d0 = g_head[(size_t)(18 + a * 4 + 0) * NPIX + p];
    float d1 = g_head[(size_t)(18 + a * 4 + 1) * NPIX + p];
    float d2 = g_head[(size_t)(18 + a * 4 + 2) * NPIX + p];
    float d3 = g_head[(size_t)(18 + a * 4 + 3) * NPIX + p];

    float sx = (float)(w * 16);
    float sy = (float)(h * 16);
    float x1a = c_anchors[a][0] + sx;
    float y1a = c_anchors[a][1] + sy;
    float x2a = c_anchors[a][2] + sx;
    float y2a = c_anchors[a][3] + sy;
    float aw = __fadd_rn(__fsub_rn(x2a, x1a), 1.0f);
    float ah = __fadd_rn(__fsub_rn(y2a, y1a), 1.0f);
    float ax = __fadd_rn(x1a, __fmul_rn(0.5f, aw));
    float ay = __fadd_rn(y1a, __fmul_rn(0.5f, ah));

    float px = __fadd_rn(__fmul_rn(d0, aw), ax);
    float py = __fadd_rn(__fmul_rn(d1, ah), ay);
    float pwv = __fmul_rn((float)exp((double)d2), aw);
    float phv = __fmul_rn((float)exp((double)d3), ah);

    float x1 = __fsub_rn(px, __fmul_rn(0.5f, pwv));
    float y1 = __fsub_rn(py, __fmul_rn(0.5f, phv));
    float x2 = __fadd_rn(px, __fmul_rn(0.5f, pwv));
    float y2 = __fadd_rn(py, __fmul_rn(0.5f, phv));

    float hiX = __fsub_rn(iminfo[1], 1.0f);
    float hiY = __fsub_rn(iminfo[0], 1.0f);
    x1 = fminf(fmaxf(x1, 0.f), hiX);
    y1 = fminf(fmaxf(y1, 0.f), hiY);
    x2 = fminf(fmaxf(x2, 0.f), hiX);
    y2 = fminf(fmaxf(y2, 0.f), hiY);

    float ws = __fadd_rn(__fsub_rn(x2, x1), 1.0f);
    float hs = __fadd_rn(__fsub_rn(y2, y1), 1.0f);
    float msz = __fmul_rn(16.0f, iminfo[2]);
    bool valid = (ws >= msz) && (hs >= msz);
    float score = valid ? fg : -1000000000.0f;

    unsigned u = __float_as_uint(score);
    u = (u & 0x80000000u) ? ~u : (u | 0x80000000u);
    g_keys[idx] = ((unsigned long long)u << 32) | (unsigned)(~(unsigned)idx);
    g_boxes[idx] = make_float4(x1, y1, x2, y2);
    atomicAdd(&g_hist1[u >> 20], 1);
}

// ---------- level-1 scan: find bucket containing rank PRE_NMS (descending)
__global__ __launch_bounds__(128) void scan1_kernel()
{
    __shared__ int part[128];
    int t = threadIdx.x;
    int s = 0;
#pragma unroll
    for (int q = 0; q < 32; q++) s += g_hist1[t * 32 + q];
    part[t] = s;
    __syncthreads();
    if (t == 0) {
        int cum = 0, seg = 0;
        for (int pp = 127; pp >= 0; pp--) {
            if (cum + part[pp] >= PRE_NMS_N) { seg = pp; break; }
            cum += part[pp];
            if (pp == 0) seg = 0;
        }
        int b = seg * 32 + 31;
        for (; b >= seg * 32; b--) {
            int c = g_hist1[b];
            if (cum + c >= PRE_NMS_N) break;
            cum += c;
        }
        if (b < seg * 32) b = seg * 32;
        g_b1 = b;
        g_above1 = cum;
    }
}

// ---------- level-2 histogram within threshold bucket
__global__ void hist2_kernel()
{
    int idx = blockIdx.x * 256 + threadIdx.x;
    if (idx >= NANCH) return;
    unsigned u = (unsigned)(g_keys[idx] >> 32);
    if ((int)(u >> 20) == g_b1)
        atomicAdd(&g_hist2[(u >> 8) & 0xFFF], 1);
}

__global__ __launch_bounds__(128) void scan2_kernel()
{
    __shared__ int part[128];
    int t = threadIdx.x;
    int s = 0;
#pragma unroll
    for (int q = 0; q < 32; q++) s += g_hist2[t * 32 + q];
    part[t] = s;
    __syncthreads();
    if (t == 0) {
        int cum = g_above1, seg = 0;
        for (int pp = 127; pp >= 0; pp--) {
            if (cum + part[pp] >= PRE_NMS_N) { seg = pp; break; }
            cum += part[pp];
            if (pp == 0) seg = 0;
        }
        int b = seg * 32 + 31;
        for (; b >= seg * 32; b--) {
            int c = g_hist2[b];
            if (cum + c >= PRE_NMS_N) break;
            cum += c;
        }
        if (b < seg * 32) b = seg * 32;
        g_T24 = ((unsigned)g_b1 << 12) | (unsigned)b;
    }
}

// ---------- compact candidates (score top-24 bits >= threshold)
__global__ void compact_kernel()
{
    int idx = blockIdx.x * 256 + threadIdx.x;
    if (idx >= NANCH) return;
    unsigned long long key = g_keys[idx];
    unsigned u = (unsigned)(key >> 32);
    if ((u >> 8) >= g_T24) {
        int pos = atomicAdd(&g_count, 1);
        if (pos < NCAND) g_cand[pos] = key;
    }
}

// ---------- bitonic sort of 8192 candidates, descending
__device__ __forceinline__ bool bt_sw(unsigned long long a, unsigned long long b, bool up)
{
    return up ? (a > b) : (a < b);
}

__global__ __launch_bounds__(1024) void cand_local_kernel()
{
    __shared__ unsigned long long s[4096];
    int base = blockIdx.x * 4096;
    for (int e = threadIdx.x; e < 4096; e += 1024) s[e] = g_cand[base + e];
    __syncthreads();
    for (int k = 2; k <= 4096; k <<= 1) {
        for (int j = k >> 1; j > 0; j >>= 1) {
            for (int t = threadIdx.x; t < 2048; t += 1024) {
                int i1 = ((t & ~(j - 1)) << 1) | (t & (j - 1));
                int i2 = i1 + j;
                bool up = (((base + i1) & k) != 0);
                unsigned long long a = s[i1], b = s[i2];
                if (bt_sw(a, b, up)) { s[i1] = b; s[i2] = a; }
            }
            __syncthreads();
        }
    }
    for (int e = threadIdx.x; e < 4096; e += 1024) g_cand[base + e] = s[e];
}

__global__ __launch_bounds__(256) void cand_global_kernel(int k, int j)
{
    int t = blockIdx.x * 256 + threadIdx.x;
    int i1 = ((t & ~(j - 1)) << 1) | (t & (j - 1));
    int i2 = i1 + j;
    bool up = ((i1 & k) != 0);
    unsigned long long a = g_cand[i1], b = g_cand[i2];
    if (bt_sw(a, b, up)) { g_cand[i1] = b; g_cand[i2] = a; }
}

__global__ __launch_bounds__(1024) void cand_fused_kernel(int k)
{
    __shared__ unsigned long long s[4096];
    int base = blockIdx.x * 4096;
    for (int e = threadIdx.x; e < 4096; e += 1024) s[e] = g_cand[base + e];
    __syncthreads();
    for (int j = 2048; j > 0; j >>= 1) {
        for (int t = threadIdx.x; t < 2048; t += 1024) {
            int i1 = ((t & ~(j - 1)) << 1) | (t & (j - 1));
            int i2 = i1 + j;
            bool up = (((base + i1) & k) != 0);
            unsigned long long a = s[i1], b = s[i2];
            if (bt_sw(a, b, up)) { s[i1] = b; s[i2] = a; }
        }
        __syncthreads();
    }
    for (int e = threadIdx.x; e < 4096; e += 1024) g_cand[base + e] = s[e];
}

__global__ void gather_kernel()
{
    int i = blockIdx.x * 256 + threadIdx.x;
    if (i >= PRE_NMS_N) return;
    unsigned idx = ~((unsigned)(g_cand[i] & 0xFFFFFFFFULL));
    g_top_boxes[i] = g_boxes[idx];
}

// ---------- NMS bitmask (upper triangle only; lower stays BSS zero)
__global__ __launch_bounds__(64) void nms_mask_kernel()
{
    int rb = blockIdx.y, cb = blockIdx.x;
    if (cb < rb) return;
    __shared__ float4 cbox[64];
    int tid = threadIdx.x;
    int col0 = cb * 64;
    int ccount = min(PRE_NMS_N - col0, 64);
    if (tid < ccount) cbox[tid] = g_top_boxes[col0 + tid];
    __syncthreads();
    int i = rb * 64 + tid;
    if (i >= PRE_NMS_N) return;
    float4 bi = g_top_boxes[i];
    float ai = __fmul_rn(__fadd_rn(__fsub_rn(bi.z, bi.x), 1.0f),
                         __fadd_rn(__fsub_rn(bi.w, bi.y), 1.0f));
    unsigned long long bits = 0ULL;
    for (int c = 0; c < ccount; c++) {
        int j = col0 + c;
        if (j <= i) continue;
        float4 bj = cbox[c];
        float xx1 = fmaxf(bi.x, bj.x);
        float yy1 = fmaxf(bi.y, bj.y);
        float xx2 = fminf(bi.z, bj.z);
        float yy2 = fminf(bi.w, bj.w);
        float iw = fmaxf(0.f, __fadd_rn(__fsub_rn(xx2, xx1), 1.0f));
        float ih = fmaxf(0.f, __fadd_rn(__fsub_rn(yy2, yy1), 1.0f));
        float inter = __fmul_rn(iw, ih);
        float aj = __fmul_rn(__fadd_rn(__fsub_rn(bj.z, bj.x), 1.0f),
                             __fadd_rn(__fsub_rn(bj.w, bj.y), 1.0f));
        float iou = __fdiv_rn(inter, __fsub_rn(__fadd_rn(ai, aj), inter));
        if (iou > 0.7f) bits |= (1ULL << c);
    }
    g_mask[(size_t)i * MASK_W + cb] = bits;
}

// ---------- warp greedy reduce with word-skip (iterates live bits only)
__global__ __launch_bounds__(32) void nms_reduce_kernel()
{
    __shared__ int keptlist[POST_NMS_N];
    const unsigned FULL = 0xffffffffu;
    int lane = threadIdx.x;
    unsigned long long remv0 = 0, remv1 = 0, remv2 = 0;
    unsigned long long kb0 = 0, kb1 = 0, kb2 = 0;
    int nkept = 0;

    for (int w = 0; w < MASK_W && nkept < POST_NMS_N; w++) {
        int owner = (w < 32) ? w : ((w < 64) ? w - 32 : w - 64);
        unsigned long long supp;
        if (w < 32)      supp = __shfl_sync(FULL, remv0, owner);
        else if (w < 64) supp = __shfl_sync(FULL, remv1, owner);
        else             supp = __shfl_sync(FULL, remv2, owner);
        unsigned long long live = ~supp;
        if (w == MASK_W - 1) live &= (1ULL << 48) - 1ULL;

        while (live && nkept < POST_NMS_N) {
            int b = __ffsll((long long)live) - 1;
            int i = (w << 6) + b;
            if (lane == 0) keptlist[nkept] = i;
            nkept++;
            if (lane == owner) {
                if (w < 32)      kb0 |= 1ULL << b;
                else if (w < 64) kb1 |= 1ULL << b;
                else             kb2 |= 1ULL << b;
            }
            const unsigned long long* row = g_mask + (size_t)i * MASK_W;
            remv0 |= row[lane];
            remv1 |= row[lane + 32];
            if (lane + 64 < MASK_W) remv2 |= row[lane + 64];
            unsigned long long supp2;
            if (w < 32)      supp2 = __shfl_sync(FULL, remv0, owner);
            else if (w < 64) supp2 = __shfl_sync(FULL, remv1, owner);
            else             supp2 = __shfl_sync(FULL, remv2, owner);
            live &= ~supp2;
            live &= ~(1ULL << b);
        }
    }

    // fill remaining slots with suppressed indices in ascending order
    for (int w = 0; w < MASK_W && nkept < POST_NMS_N; w++) {
        int owner = (w < 32) ? w : ((w < 64) ? w - 32 : w - 64);
        unsigned long long kw;
        if (w < 32)      kw = __shfl_sync(FULL, kb0, owner);
        else if (w < 64) kw = __shfl_sync(FULL, kb1, owner);
        else             kw = __shfl_sync(FULL, kb2, owner);
        unsigned long long live = ~kw;
        if (w == MASK_W - 1) live &= (1ULL << 48) - 1ULL;
        while (live && nkept < POST_NMS_N) {
            int b = __ffsll((long long)live) - 1;
            if (lane == 0) keptlist[nkept] = (w << 6) + b;
            nkept++;
            live &= live - 1;
        }
    }
    __syncwarp();
    for (int t = lane; t < POST_NMS_N; t += 32) g_sel[t] = keptlist[t];
}

__global__ void rois_kernel(float* __restrict__ out)
{
    int t = blockIdx.x * 64 + threadIdx.x;
    if (t >= POST_NMS_N) return;
    float4 b = g_top_boxes[g_sel[t]];
    out[t * 5 + 0] = 0.f;
    out[t * 5 + 1] = b.x;
    out[t * 5 + 2] = b.y;
    out[t * 5 + 3] = b.z;
    out[t * 5 + 4] = b.w;
}

extern "C" void kernel_launch(void* const* d_in, const int* in_sizes, int n_in,
                              void* d_out, int out_size)
{
    const float* feature_map = (const float*)d_in[0];
    const float* im_info     = (const float*)d_in[1];
    const float* conv_w      = (const float*)d_in[2];
    const float* conv_b      = (const float*)d_in[3];
    const float* cls_w       = (const float*)d_in[4];
    const float* cls_b       = (const float*)d_in[5];
    const float* bbox_w      = (const float*)d_in[6];
    const float* bbox_b      = (const float*)d_in[7];
    float* out = (float*)d_out;

    wtrans_kernel<<<(COUT * KTOT + 255) / 256, 256>>>(conv_w);

    dim3 cgrid((NPIX + 127) / 128, 4);
    conv3x3_kernel<<<cgrid, 128>>>(feature_map, conv_b);

    zero_sel_kernel<<<(NCAND + 255) / 256, 256>>>();
    head_kernel<<<(NPIX + 127) / 128, 256>>>(cls_w, cls_b, bbox_w, bbox_b);
    decode_kernel<<<(NANCH + 255) / 256, 256>>>(im_info);

    scan1_kernel<<<1, 128>>>();
    hist2_kernel<<<(NANCH + 255) / 256, 256>>>();
    scan2_kernel<<<1, 128>>>();
    compact_kernel<<<(NANCH + 255) / 256, 256>>>();

    cand_local_kernel<<<NCAND / 4096, 1024>>>();
    cand_global_kernel<<<NCAND / 512, 256>>>(NCAND, NCAND / 2);
    cand_fused_kernel<<<NCAND / 4096, 1024>>>(NCAND);

    gather_kernel<<<(PRE_NMS_N + 255) / 256, 256>>>();
    dim3 mgrid(MASK_W, MASK_W);
    nms_mask_kernel<<<mgrid, 64>>>();
    nms_reduce_kernel<<<1, 32>>>();
    rois_kernel<<<(POST_NMS_N + 63) / 64, 64>>>(out);
}